// round 4
// baseline (speedup 1.0000x reference)
#include <cuda_runtime.h>
#include <math.h>

#define B_   16
#define C_   1024
#define CH_  512
#define HW_  4096
#define K_   1024

#define BM 128
#define BN 128
#define BK 16
#define TM 8
#define TN 8
#define NT 256   // threads per block

// ---- scratch (device globals; every slot written every launch, no zero-init needed) ----
__device__ float g_q[B_*HW_];            // relu(x . w_qr), pre-softmax
__device__ float g_mask[B_*HW_];         // softmax(q)
__device__ float g_qlpart[B_*32*CH_];    // per-ntile colsums of relu(x.w_ql)
__device__ float g_ctxpart[B_*32*CH_];   // per-ntile   sum_n relu(x.w_vr)*mask
__device__ float g_chanpart[B_*4*HW_];   // per-ctile   sum_c avgx*relu(x.w_vl)
__device__ float g_avgx[B_*CH_];         // softmax(mean(g_x))
__device__ float g_spatial[B_*CH_];      // sigmoid(layernorm(context))
__device__ float g_chattn[B_*HW_];       // sigmoid(channel logits)

// ======================= fused tiled GEMM =======================
// pass 0: yt=0..3 -> w_ql ctile yt, epilogue colsum -> g_qlpart; yt==0 blocks also
//         compute q[n] = relu(sum_k x[k,n]*w_qr[k]) for their n-range.
// pass 1: yt=0..3 -> w_vr ctile yt, epilogue sum_n relu*mask -> g_ctxpart
//         yt=4..7 -> w_vl ctile yt-4, epilogue sum_c avgx*relu -> g_chanpart
__global__ __launch_bounds__(NT, 2)
void gemm_fused(const float* __restrict__ x,
                const float* __restrict__ w_qr,
                const float* __restrict__ w_vr,
                const float* __restrict__ w_ql,
                const float* __restrict__ w_vl,
                int pass)
{
    const int b  = blockIdx.z;
    const int nt = blockIdx.x;
    const int yt = blockIdx.y;

    const float* w;
    int ctile, epi;          // epi: 0=colsum, 1=ctx, 2=chan
    bool do_q = false;
    if (pass == 0)      { ctile = yt;     w = w_ql; epi = 0; do_q = (yt == 0); }
    else if (yt < 4)    { ctile = yt;     w = w_vr; epi = 1; }
    else                { ctile = yt - 4; w = w_vl; epi = 2; }

    const int c0 = ctile * BM;
    const int n0 = nt * BN;
    const float* xb = x + (size_t)b * C_ * HW_;

    __shared__ float As[2][BK][BM];
    __shared__ float Bs[2][BK][BN];
    __shared__ float sWq[K_];

    const int t = threadIdx.x;
    if (pass == 0) {
        for (int i = t; i < K_; i += NT) sWq[i] = w_qr[i];
    }

    // global->smem load mapping (512 float4 per operand per stage, 2 per thread)
    const int aC0 = (t      ) >> 2, aK0 = ((t      ) & 3) * 4;
    const int aC1 = (t + 256) >> 2, aK1 = ((t + 256) & 3) * 4;
    const int bK0 = (t      ) >> 5, bN0 = ((t      ) & 31) * 4;
    const int bK1 = (t + 256) >> 5, bN1 = ((t + 256) & 31) * 4;

    const int rowBase = (t >> 4) * TM;   // c within tile
    const int colBase = (t & 15) * TN;   // n within tile

    float acc[TM][TN];
    #pragma unroll
    for (int i = 0; i < TM; i++)
        #pragma unroll
        for (int j = 0; j < TN; j++) acc[i][j] = 0.f;

    float qacc = 0.f;

    // prologue: stage 0
    {
        float4 a0 = *(const float4*)&w [(size_t)(c0 + aC0) * K_ + aK0];
        float4 a1 = *(const float4*)&w [(size_t)(c0 + aC1) * K_ + aK1];
        float4 b0 = *(const float4*)&xb[(size_t)(bK0) * HW_ + n0 + bN0];
        float4 b1 = *(const float4*)&xb[(size_t)(bK1) * HW_ + n0 + bN1];
        As[0][aK0+0][aC0] = a0.x; As[0][aK0+1][aC0] = a0.y;
        As[0][aK0+2][aC0] = a0.z; As[0][aK0+3][aC0] = a0.w;
        As[0][aK1+0][aC1] = a1.x; As[0][aK1+1][aC1] = a1.y;
        As[0][aK1+2][aC1] = a1.z; As[0][aK1+3][aC1] = a1.w;
        *(float4*)&Bs[0][bK0][bN0] = b0;
        *(float4*)&Bs[0][bK1][bN1] = b1;
    }
    __syncthreads();

    const int NKT = K_ / BK;
    for (int kt = 0; kt < NKT; kt++) {
        const int cur = kt & 1, nxt = cur ^ 1;
        float4 a0, a1, b0, b1;
        const bool pf = (kt + 1 < NKT);
        if (pf) {
            const int k0 = (kt + 1) * BK;
            a0 = *(const float4*)&w [(size_t)(c0 + aC0) * K_ + k0 + aK0];
            a1 = *(const float4*)&w [(size_t)(c0 + aC1) * K_ + k0 + aK1];
            b0 = *(const float4*)&xb[(size_t)(k0 + bK0) * HW_ + n0 + bN0];
            b1 = *(const float4*)&xb[(size_t)(k0 + bK1) * HW_ + n0 + bN1];
        }
        #pragma unroll
        for (int kk = 0; kk < BK; kk++) {
            float a[TM], bb[TN];
            *(float4*)&a [0] = *(const float4*)&As[cur][kk][rowBase    ];
            *(float4*)&a [4] = *(const float4*)&As[cur][kk][rowBase + 4];
            *(float4*)&bb[0] = *(const float4*)&Bs[cur][kk][colBase    ];
            *(float4*)&bb[4] = *(const float4*)&Bs[cur][kk][colBase + 4];
            #pragma unroll
            for (int i = 0; i < TM; i++)
                #pragma unroll
                for (int j = 0; j < TN; j++)
                    acc[i][j] = fmaf(a[i], bb[j], acc[i][j]);
        }
        if (do_q && t < BN) {
            #pragma unroll
            for (int kk = 0; kk < BK; kk++)
                qacc = fmaf(Bs[cur][kk][t], sWq[kt * BK + kk], qacc);
        }
        if (pf) {
            As[nxt][aK0+0][aC0] = a0.x; As[nxt][aK0+1][aC0] = a0.y;
            As[nxt][aK0+2][aC0] = a0.z; As[nxt][aK0+3][aC0] = a0.w;
            As[nxt][aK1+0][aC1] = a1.x; As[nxt][aK1+1][aC1] = a1.y;
            As[nxt][aK1+2][aC1] = a1.z; As[nxt][aK1+3][aC1] = a1.w;
            *(float4*)&Bs[nxt][bK0][bN0] = b0;
            *(float4*)&Bs[nxt][bK1][bN1] = b1;
            __syncthreads();
        }
    }

    // ---- epilogue ----
    if (epi == 0 || epi == 1) {
        float m[TN];
        if (epi == 1) {
            #pragma unroll
            for (int j = 0; j < TN; j++)
                m[j] = g_mask[b * HW_ + n0 + colBase + j];
        } else {
            #pragma unroll
            for (int j = 0; j < TN; j++) m[j] = 1.f;
        }
        float* outp = (epi == 0) ? g_qlpart : g_ctxpart;
        #pragma unroll
        for (int i = 0; i < TM; i++) {
            float v = 0.f;
            #pragma unroll
            for (int j = 0; j < TN; j++)
                v = fmaf(fmaxf(acc[i][j], 0.f), m[j], v);
            #pragma unroll
            for (int off = 8; off; off >>= 1)
                v += __shfl_down_sync(0xffffffffu, v, off, 16);
            if ((t & 15) == 0)
                outp[((size_t)(b * 32 + nt)) * CH_ + c0 + rowBase + i] = v;
        }
    } else {
        float av[TM];
        #pragma unroll
        for (int i = 0; i < TM; i++)
            av[i] = g_avgx[b * CH_ + c0 + rowBase + i];
        float s[TN];
        #pragma unroll
        for (int j = 0; j < TN; j++) {
            s[j] = 0.f;
            #pragma unroll
            for (int i = 0; i < TM; i++)
                s[j] = fmaf(fmaxf(acc[i][j], 0.f), av[i], s[j]);
        }
        __syncthreads();                 // done with tiles, reuse As as scratch
        float* red = &As[0][0][0];       // [16 ty][128 n]
        const int ty = t >> 4, tx = t & 15;
        #pragma unroll
        for (int j = 0; j < TN; j++)
            red[ty * BN + tx * TN + j] = s[j];
        __syncthreads();
        if (t < BN) {
            float v = 0.f;
            #pragma unroll
            for (int r = 0; r < 16; r++) v += red[r * BN + t];
            g_chanpart[((size_t)(b * 4 + ctile)) * HW_ + n0 + t] = v;
        }
    }
    if (do_q && t < BN)
        g_q[b * HW_ + n0 + t] = fmaxf(qacc, 0.f);
}

// ======================= block reductions =======================
__device__ __forceinline__ float bsum256(float v, float* sm) {
    const int t = threadIdx.x;
    #pragma unroll
    for (int off = 16; off; off >>= 1) v += __shfl_down_sync(0xffffffffu, v, off);
    if ((t & 31) == 0) sm[t >> 5] = v;
    __syncthreads();
    if (t == 0) {
        float s = 0.f;
        #pragma unroll
        for (int i = 0; i < NT / 32; i++) s += sm[i];
        sm[0] = s;
    }
    __syncthreads();
    float r = sm[0];
    __syncthreads();
    return r;
}
__device__ __forceinline__ float bmax256(float v, float* sm) {
    const int t = threadIdx.x;
    #pragma unroll
    for (int off = 16; off; off >>= 1) v = fmaxf(v, __shfl_down_sync(0xffffffffu, v, off));
    if ((t & 31) == 0) sm[t >> 5] = v;
    __syncthreads();
    if (t == 0) {
        float s = -1e30f;
        #pragma unroll
        for (int i = 0; i < NT / 32; i++) s = fmaxf(s, sm[i]);
        sm[0] = s;
    }
    __syncthreads();
    float r = sm[0];
    __syncthreads();
    return r;
}

// ============ pass 2: mask softmax + avg_x softmax ============
__global__ void softmax_kernel()
{
    __shared__ float sred[32];
    __shared__ float sbuf[CH_];
    const int b = blockIdx.x, t = threadIdx.x;

    // mask = softmax over hw of q
    const float* q = g_q + (size_t)b * HW_;
    float mx = -1e30f;
    for (int i = t; i < HW_; i += NT) mx = fmaxf(mx, q[i]);
    mx = bmax256(mx, sred);
    float sum = 0.f;
    for (int i = t; i < HW_; i += NT) sum += expf(q[i] - mx);
    sum = bsum256(sum, sred);
    const float inv = 1.f / sum;
    for (int i = t; i < HW_; i += NT)
        g_mask[(size_t)b * HW_ + i] = expf(q[i] - mx) * inv;

    // avg_x = softmax over ch of mean_hw(relu(x.w_ql))
    for (int c = t; c < CH_; c += NT) {
        float g = 0.f;
        for (int n = 0; n < 32; n++)
            g += g_qlpart[((size_t)(b * 32 + n)) * CH_ + c];
        sbuf[c] = g * (1.f / HW_);
    }
    __syncthreads();
    float mx2 = -1e30f;
    for (int c = t; c < CH_; c += NT) mx2 = fmaxf(mx2, sbuf[c]);
    mx2 = bmax256(mx2, sred);
    float s2 = 0.f;
    for (int c = t; c < CH_; c += NT) s2 += expf(sbuf[c] - mx2);
    s2 = bsum256(s2, sred);
    const float inv2 = 1.f / s2;
    for (int c = t; c < CH_; c += NT)
        g_avgx[(size_t)b * CH_ + c] = expf(sbuf[c] - mx2) * inv2;
}

// ===== pass 4: layernorm+sigmoid (spatial) and sigmoid (channel) =====
__global__ void finalize_kernel()
{
    __shared__ float sred[32];
    __shared__ float sv[CH_];
    const int b = blockIdx.x, t = threadIdx.x;

    for (int c = t; c < CH_; c += NT) {
        float v = 0.f;
        for (int n = 0; n < 32; n++)
            v += g_ctxpart[((size_t)(b * 32 + n)) * CH_ + c];
        sv[c] = v;
    }
    __syncthreads();
    float ls = 0.f;
    for (int c = t; c < CH_; c += NT) ls += sv[c];
    const float mu = bsum256(ls, sred) * (1.f / CH_);
    float lv = 0.f;
    for (int c = t; c < CH_; c += NT) { float d = sv[c] - mu; lv += d * d; }
    const float var = bsum256(lv, sred) * (1.f / CH_);
    const float rs = rsqrtf(var + 1e-5f);
    for (int c = t; c < CH_; c += NT) {
        float z = (sv[c] - mu) * rs;
        g_spatial[(size_t)b * CH_ + c] = 1.f / (1.f + expf(-z));
    }

    for (int n = t; n < HW_; n += NT) {
        float cl = 0.f;
        #pragma unroll
        for (int k = 0; k < 4; k++)
            cl += g_chanpart[((size_t)(b * 4 + k)) * HW_ + n];
        g_chattn[(size_t)b * HW_ + n] = 1.f / (1.f + expf(-cl));
    }
}

// ============ pass 5: out = x * (1 + attn) ============
__global__ void output_kernel(const float* __restrict__ x, float* __restrict__ out)
{
    const int b = blockIdx.z, c = blockIdx.y;
    const int n = (blockIdx.x * NT + threadIdx.x) * 4;
    const float s = g_spatial[(size_t)b * CH_ + (c & (CH_ - 1))];
    const size_t base = ((size_t)b * C_ + c) * HW_ + n;
    float4 xv = *(const float4*)&x[base];
    float4 ch = *(const float4*)&g_chattn[(size_t)b * HW_ + n];
    float4 o;
    if (c < CH_) {
        o.x = fmaf(xv.x, s * ch.x, xv.x);
        o.y = fmaf(xv.y, s * ch.y, xv.y);
        o.z = fmaf(xv.z, s * ch.z, xv.z);
        o.w = fmaf(xv.w, s * ch.w, xv.w);
    } else {
        o.x = fmaf(xv.x, s + ch.x, xv.x);
        o.y = fmaf(xv.y, s + ch.y, xv.y);
        o.z = fmaf(xv.z, s + ch.z, xv.z);
        o.w = fmaf(xv.w, s + ch.w, xv.w);
    }
    *(float4*)&out[base] = o;
}

// ======================= launch =======================
extern "C" void kernel_launch(void* const* d_in, const int* in_sizes, int n_in,
                              void* d_out, int out_size)
{
    (void)in_sizes; (void)n_in; (void)out_size;
    const float* x    = (const float*)d_in[0];
    const float* w_qr = (const float*)d_in[1];
    const float* w_vr = (const float*)d_in[2];
    const float* w_ql = (const float*)d_in[3];
    const float* w_vl = (const float*)d_in[4];
    float* out = (float*)d_out;

    dim3 g1(HW_ / BN, CH_ / BM, B_);         // 32 x 4 x 16
    gemm_fused<<<g1, NT>>>(x, w_qr, w_vr, w_ql, w_vl, 0);

    softmax_kernel<<<B_, NT>>>();

    dim3 g3(HW_ / BN, 2 * CH_ / BM, B_);     // 32 x 8 x 16
    gemm_fused<<<g3, NT>>>(x, w_qr, w_vr, w_ql, w_vl, 1);

    finalize_kernel<<<B_, NT>>>();

    dim3 g5(HW_ / (NT * 4), C_, B_);         // 4 x 1024 x 16
    output_kernel<<<g5, NT>>>(x, out);
}